// round 5
// baseline (speedup 1.0000x reference)
#include <cuda_runtime.h>
#include <cstddef>
#include <cstdint>

#define BATCH 64
#define SEQ   2048
#define DIM   512
#define NFINE 16
#define MSPAN 512

typedef unsigned long long u64;

// Blackwell packed fp32x2 math (SASS FFMA2/FADD2) — PTX-only.
#define FMA2(d,a,b,c) asm("fma.rn.f32x2 %0, %1, %2, %3;" : "=l"(d) : "l"(a), "l"(b), "l"(c))
#define ADD2(d,a,b)   asm("add.rn.f32x2 %0, %1, %2;" : "=l"(d) : "l"(a), "l"(b))

// g_ctr[0] = total valid spans, g_ctr[1] = dynamic fetch ticket.
// Reset each launch by an 8-byte cudaMemsetAsync (graph-capturable).
__device__ int g_ctr[2];
__device__ int g_spanP[BATCH * MSPAN];  // span start token (global index)
__device__ int g_spanE[BATCH * MSPAN];  // span end token (global index, exclusive)
__device__ int g_spanW[BATCH * MSPAN];  // output span slot (b*MSPAN + k)

// ---------------------------------------------------------------------------
// Kernel A: per batch row, compact B-tag positions via block scan, emit
// (start, end, out_idx) triples to the global compact worklist.
// ---------------------------------------------------------------------------
__global__ void __launch_bounds__(256) span_index_kernel(
    const int* __restrict__ labels, const int* __restrict__ pB)
{
    __shared__ int Bpos[MSPAN + 1];
    __shared__ int s_base, s_n, s_nbtot;
    __shared__ int wsum[8];

    const int b = blockIdx.x;
    const int t = threadIdx.x;
    const int cB = *pB;
    const int* row = labels + (size_t)b * SEQ;

    const int s0 = t * 8;
    int flags[8];
    int cnt = 0;
#pragma unroll
    for (int j = 0; j < 8; j++) {
        flags[j] = (row[s0 + j] == cB) ? 1 : 0;
        cnt += flags[j];
    }

    const int lane = t & 31;
    const int warp = t >> 5;
    int inc = cnt;
#pragma unroll
    for (int o = 1; o < 32; o <<= 1) {
        int v = __shfl_up_sync(0xffffffffu, inc, o);
        if (lane >= o) inc += v;
    }
    if (lane == 31) wsum[warp] = inc;
    __syncthreads();
    if (t < 8) {
        int v = wsum[t];
#pragma unroll
        for (int o = 1; o < 8; o <<= 1) {
            int u = __shfl_up_sync(0xffu, v, o);
            if (t >= o) v += u;
        }
        wsum[t] = v;
    }
    __syncthreads();
    int excl = inc - cnt + (warp > 0 ? wsum[warp - 1] : 0);

    int idx = excl;
#pragma unroll
    for (int j = 0; j < 8; j++) {
        if (flags[j]) {
            if (idx <= MSPAN) Bpos[idx] = s0 + j;
            idx++;
        }
    }
    if (t == 255) {
        int nBtot = excl + cnt;
        int n = nBtot < MSPAN ? nBtot : MSPAN;
        s_nbtot = nBtot;
        s_n = n;
        s_base = atomicAdd(&g_ctr[0], n);
    }
    __syncthreads();

    const int n = s_n;
    const int base = s_base;
    const int nbtot = s_nbtot;
    for (int k = t; k < n; k += 256) {
        int p = Bpos[k];
        // k+1 <= MSPAN always; Bpos[k+1] was written iff a (k+1)-th B exists.
        int pend = (k + 1 < nbtot) ? Bpos[k + 1] : SEQ;
        g_spanP[base + k] = b * SEQ + p;
        g_spanE[base + k] = b * SEQ + pend;
        g_spanW[base + k] = b * MSPAN + k;
    }
}

// ---------------------------------------------------------------------------
// Tree-fold 4 per-lane partials across the warp in 6 SHFLs; 4 lanes write.
// ---------------------------------------------------------------------------
__device__ __forceinline__ void fold_write(
    const float sc[4], bool valid, float* __restrict__ dst, int lane)
{
    float send0 = (lane & 16) ? sc[0] : sc[2];
    float r0 = __shfl_xor_sync(0xffffffffu, send0, 16);
    float n0 = ((lane & 16) ? sc[2] : sc[0]) + r0;
    float send1 = (lane & 16) ? sc[1] : sc[3];
    float r1 = __shfl_xor_sync(0xffffffffu, send1, 16);
    float n1 = ((lane & 16) ? sc[3] : sc[1]) + r1;

    float send = (lane & 8) ? n0 : n1;
    float r = __shfl_xor_sync(0xffffffffu, send, 8);
    float v = ((lane & 8) ? n1 : n0) + r;

    v += __shfl_xor_sync(0xffffffffu, v, 4);
    v += __shfl_xor_sync(0xffffffffu, v, 2);
    v += __shfl_xor_sync(0xffffffffu, v, 1);

    if (valid && (lane & 7) == 0) {
        int floc = (((lane >> 4) & 1) << 1) | ((lane >> 3) & 1);
        dst[floc] = v;
    }
}

// ---------------------------------------------------------------------------
// Kernel B: persistent warps, dynamic 4-span tickets. All 4 spans' head rows
// + label blocks issue as one independent LDG batch (deep MLP); projection
// shares every W LDS.128 across 4 spans; packed f32x2 math.
// ---------------------------------------------------------------------------
__global__ void __launch_bounds__(256, 2) span_project_kernel(
    const float* __restrict__ hidden,
    const float* __restrict__ slot,   // [DIM][NFINE]
    const int*   __restrict__ labels, // flat [BATCH*SEQ]
    const int*   __restrict__ pI,
    float* __restrict__ out)          // [BATCH][MSPAN][NFINE]
{
    __shared__ __align__(16) float Wsh[NFINE * DIM];  // Wsh[f*512 + d]
    for (int i = threadIdx.x; i < DIM * NFINE; i += blockDim.x) {
        int d = i >> 4;
        int f = i & 15;
        Wsh[f * DIM + d] = slot[i];
    }
    __syncthreads();
    const ulonglong2* W2 = reinterpret_cast<const ulonglong2*>(Wsh);

    const int cI = *pI;
    const int lane = threadIdx.x & 31;
    const int total = g_ctr[0];

    for (;;) {
        int i;
        if (lane == 0) i = atomicAdd(&g_ctr[1], 4);
        i = __shfl_sync(0xffffffffu, i, 0);
        if (i >= total) break;

        bool v[4];
        int P[4], E[4], O[4];
#pragma unroll
        for (int j = 0; j < 4; j++) {
            int idx = i + j;
            v[j] = (idx < total);
            P[j] = v[j] ? __ldg(g_spanP + idx) : __ldg(g_spanP + i);
            E[j] = v[j] ? __ldg(g_spanE + idx) : P[j];  // empty scan if invalid
            O[j] = v[j] ? __ldg(g_spanW + idx) : 0;
        }

        // ---- head rows of all 4 spans: 16 independent LDG.128 ----
        u64 F[4][8];
#pragma unroll
        for (int j = 0; j < 4; j++) {
            const ulonglong2* h =
                reinterpret_cast<const ulonglong2*>(hidden + (size_t)P[j] * DIM);
            ulonglong2 a = __ldg(h + lane);
            ulonglong2 bq = __ldg(h + lane + 32);
            ulonglong2 c = __ldg(h + lane + 64);
            ulonglong2 d = __ldg(h + lane + 96);
            F[j][0] = a.x;  F[j][1] = a.y;  F[j][2] = bq.x; F[j][3] = bq.y;
            F[j][4] = c.x;  F[j][5] = c.y;  F[j][6] = d.x;  F[j][7] = d.y;
        }

        // ---- interleaved I-token accumulation across 4 spans ----
        unsigned m[4] = {0u, 0u, 0u, 0u};
        int s[4];
#pragma unroll
        for (int j = 0; j < 4; j++) s[j] = P[j] + 1;

        for (;;) {
#pragma unroll
            for (int j = 0; j < 4; j++) {
                if (m[j] == 0 && s[j] < E[j]) {
                    int ss = s[j] + lane;
                    bool hit = (ss < E[j]) && (__ldg(labels + ss) == cI);
                    m[j] = __ballot_sync(0xffffffffu, hit);
                    s[j] += 32;
                }
            }
            bool done = true, anyrow = false;
            int tk[4];
#pragma unroll
            for (int j = 0; j < 4; j++) {
                tk[j] = -1;
                if (m[j]) {
                    int jj = __ffs(m[j]) - 1;
                    m[j] &= m[j] - 1;
                    tk[j] = s[j] - 32 + jj;
                    anyrow = true;
                }
                if (m[j] || s[j] < E[j]) done = false;
            }
            if (!anyrow) {
                if (done) break;
                continue;
            }

            ulonglong2 r[4][4];
#pragma unroll
            for (int j = 0; j < 4; j++) {
                if (tk[j] >= 0) {
                    const ulonglong2* h =
                        reinterpret_cast<const ulonglong2*>(hidden + (size_t)tk[j] * DIM);
                    r[j][0] = __ldg(h + lane);
                    r[j][1] = __ldg(h + lane + 32);
                    r[j][2] = __ldg(h + lane + 64);
                    r[j][3] = __ldg(h + lane + 96);
                }
            }
#pragma unroll
            for (int j = 0; j < 4; j++) {
                if (tk[j] >= 0) {
                    ADD2(F[j][0], F[j][0], r[j][0].x); ADD2(F[j][1], F[j][1], r[j][0].y);
                    ADD2(F[j][2], F[j][2], r[j][1].x); ADD2(F[j][3], F[j][3], r[j][1].y);
                    ADD2(F[j][4], F[j][4], r[j][2].x); ADD2(F[j][5], F[j][5], r[j][2].y);
                    ADD2(F[j][6], F[j][6], r[j][3].x); ADD2(F[j][7], F[j][7], r[j][3].y);
                }
            }
        }

        // ---- projection: W LDS shared across all 4 spans ----
#pragma unroll
        for (int g = 0; g < 4; g++) {
            float sc[4][4];
#pragma unroll
            for (int jj = 0; jj < 4; jj++) {
                const int f = 4 * g + jj;
                ulonglong2 wa = W2[f * 128 + lane];
                ulonglong2 wb = W2[f * 128 + lane + 32];
                ulonglong2 wc = W2[f * 128 + lane + 64];
                ulonglong2 wd = W2[f * 128 + lane + 96];
#pragma unroll
                for (int j = 0; j < 4; j++) {
                    u64 acc = 0ull;
                    FMA2(acc, F[j][0], wa.x, acc);
                    FMA2(acc, F[j][1], wa.y, acc);
                    FMA2(acc, F[j][2], wb.x, acc);
                    FMA2(acc, F[j][3], wb.y, acc);
                    FMA2(acc, F[j][4], wc.x, acc);
                    FMA2(acc, F[j][5], wc.y, acc);
                    FMA2(acc, F[j][6], wd.x, acc);
                    FMA2(acc, F[j][7], wd.y, acc);
                    float2 p = *reinterpret_cast<float2*>(&acc);
                    sc[j][jj] = p.x + p.y;
                }
            }
#pragma unroll
            for (int j = 0; j < 4; j++) {
                fold_write(sc[j], v[j], out + (size_t)O[j] * NFINE + 4 * g, lane);
            }
        }
    }
}

extern "C" void kernel_launch(void* const* d_in, const int* in_sizes, int n_in,
                              void* d_out, int out_size)
{
    const float* hidden = (const float*)d_in[0];
    const float* slot   = (const float*)d_in[1];
    const int*   labels = (const int*)d_in[2];
    const int*   pB     = (const int*)d_in[3];
    const int*   pI     = (const int*)d_in[4];
    float* out = (float*)d_out;

    void* ctr_ptr = nullptr;
    cudaGetSymbolAddress(&ctr_ptr, g_ctr);
    cudaMemsetAsync(ctr_ptr, 0, 2 * sizeof(int), 0);
    cudaMemsetAsync(out, 0, (size_t)out_size * sizeof(float), 0);

    span_index_kernel<<<BATCH, 256>>>(labels, pB);
    span_project_kernel<<<148 * 2, 256>>>(hidden, slot, labels, pI, out);
}

// round 6
// speedup vs baseline: 1.0259x; 1.0259x over previous
#include <cuda_runtime.h>
#include <cstddef>
#include <cstdint>

#define BATCH 64
#define SEQ   2048
#define DIM   512
#define NFINE 16
#define MSPAN 512

typedef unsigned long long u64;

// Blackwell packed fp32x2 math (SASS FFMA2/FADD2) — PTX-only.
#define FMA2(d,a,b,c) asm("fma.rn.f32x2 %0, %1, %2, %3;" : "=l"(d) : "l"(a), "l"(b), "l"(c))
#define ADD2(d,a,b)   asm("add.rn.f32x2 %0, %1, %2;" : "=l"(d) : "l"(a), "l"(b))

// g_ctr[0] = total valid spans, g_ctr[1] = dynamic fetch ticket.
// Reset each launch by an 8-byte cudaMemsetAsync (graph-capturable).
__device__ int g_ctr[2];
__device__ int g_spanP[BATCH * MSPAN];  // span start token (global index)
__device__ int g_spanE[BATCH * MSPAN];  // span end token (global, exclusive)
__device__ int g_spanW[BATCH * MSPAN];  // output span slot (b*MSPAN + k)

// ---------------------------------------------------------------------------
// Kernel A: per batch row, compact B-tag positions via block scan, emit
// (start, end, out_idx) triples to the global compact worklist.
// ---------------------------------------------------------------------------
__global__ void __launch_bounds__(256) span_index_kernel(
    const int* __restrict__ labels, const int* __restrict__ pB)
{
    __shared__ int Bpos[MSPAN + 1];
    __shared__ int s_base, s_n, s_nbtot;
    __shared__ int wsum[8];

    const int b = blockIdx.x;
    const int t = threadIdx.x;
    const int cB = *pB;
    const int* row = labels + (size_t)b * SEQ;

    const int s0 = t * 8;
    int flags[8];
    int cnt = 0;
#pragma unroll
    for (int j = 0; j < 8; j++) {
        flags[j] = (row[s0 + j] == cB) ? 1 : 0;
        cnt += flags[j];
    }

    const int lane = t & 31;
    const int warp = t >> 5;
    int inc = cnt;
#pragma unroll
    for (int o = 1; o < 32; o <<= 1) {
        int v = __shfl_up_sync(0xffffffffu, inc, o);
        if (lane >= o) inc += v;
    }
    if (lane == 31) wsum[warp] = inc;
    __syncthreads();
    if (t < 8) {
        int v = wsum[t];
#pragma unroll
        for (int o = 1; o < 8; o <<= 1) {
            int u = __shfl_up_sync(0xffu, v, o);
            if (t >= o) v += u;
        }
        wsum[t] = v;
    }
    __syncthreads();
    int excl = inc - cnt + (warp > 0 ? wsum[warp - 1] : 0);

    int idx = excl;
#pragma unroll
    for (int j = 0; j < 8; j++) {
        if (flags[j]) {
            if (idx <= MSPAN) Bpos[idx] = s0 + j;
            idx++;
        }
    }
    if (t == 255) {
        int nBtot = excl + cnt;
        int n = nBtot < MSPAN ? nBtot : MSPAN;
        s_nbtot = nBtot;
        s_n = n;
        s_base = atomicAdd(&g_ctr[0], n);
    }
    __syncthreads();

    const int n = s_n;
    const int base = s_base;
    const int nbtot = s_nbtot;
    for (int k = t; k < n; k += 256) {
        int p = Bpos[k];
        int pend = (k + 1 < nbtot) ? Bpos[k + 1] : SEQ;  // Bpos[k+1] valid iff written
        g_spanP[base + k] = b * SEQ + p;
        g_spanE[base + k] = b * SEQ + pend;
        g_spanW[base + k] = b * MSPAN + k;
    }
}

// ---------------------------------------------------------------------------
// Tree-fold 4 per-lane partials across the warp in 6 SHFLs; 4 lanes write.
// ---------------------------------------------------------------------------
__device__ __forceinline__ void fold_write(
    const float sc[4], float* __restrict__ dst, int lane)
{
    float send0 = (lane & 16) ? sc[0] : sc[2];
    float r0 = __shfl_xor_sync(0xffffffffu, send0, 16);
    float n0 = ((lane & 16) ? sc[2] : sc[0]) + r0;
    float send1 = (lane & 16) ? sc[1] : sc[3];
    float r1 = __shfl_xor_sync(0xffffffffu, send1, 16);
    float n1 = ((lane & 16) ? sc[3] : sc[1]) + r1;

    float send = (lane & 8) ? n0 : n1;
    float r = __shfl_xor_sync(0xffffffffu, send, 8);
    float v = ((lane & 8) ? n1 : n0) + r;

    v += __shfl_xor_sync(0xffffffffu, v, 4);
    v += __shfl_xor_sync(0xffffffffu, v, 2);
    v += __shfl_xor_sync(0xffffffffu, v, 1);

    if ((lane & 7) == 0) {
        int floc = (((lane >> 4) & 1) << 1) | ((lane >> 3) & 1);
        dst[floc] = v;
    }
}

// ---------------------------------------------------------------------------
// Kernel B: persistent warps, dynamic single-span tickets, minimal register
// footprint (<=64 via launch_bounds) for 4 blocks/SM occupancy.
// ---------------------------------------------------------------------------
__global__ void __launch_bounds__(256, 4) span_project_kernel(
    const float* __restrict__ hidden,
    const float* __restrict__ slot,   // [DIM][NFINE]
    const int*   __restrict__ labels, // flat [BATCH*SEQ]
    const int*   __restrict__ pI,
    float* __restrict__ out)          // [BATCH][MSPAN][NFINE]
{
    __shared__ __align__(16) float Wsh[NFINE * DIM];  // Wsh[f*512 + d]
    for (int i = threadIdx.x; i < DIM * NFINE; i += blockDim.x) {
        int d = i >> 4;
        int f = i & 15;
        Wsh[f * DIM + d] = slot[i];
    }
    __syncthreads();
    const ulonglong2* W2 = reinterpret_cast<const ulonglong2*>(Wsh);

    const int cI = *pI;
    const int lane = threadIdx.x & 31;
    const int total = g_ctr[0];

    for (;;) {
        int i;
        if (lane == 0) i = atomicAdd(&g_ctr[1], 1);
        i = __shfl_sync(0xffffffffu, i, 0);
        if (i >= total) break;

        const int P = __ldg(g_spanP + i);
        const int E = __ldg(g_spanE + i);
        const int O = __ldg(g_spanW + i);

        // head row: 4 independent LDG.128
        u64 F[8];
        {
            const ulonglong2* h =
                reinterpret_cast<const ulonglong2*>(hidden + (size_t)P * DIM);
            ulonglong2 a = __ldg(h + lane);
            ulonglong2 b = __ldg(h + lane + 32);
            ulonglong2 c = __ldg(h + lane + 64);
            ulonglong2 d = __ldg(h + lane + 96);
            F[0] = a.x; F[1] = a.y; F[2] = b.x; F[3] = b.y;
            F[4] = c.x; F[5] = c.y; F[6] = d.x; F[7] = d.y;
        }

        // I-token accumulation
        for (int s = P + 1; s < E; s += 32) {
            int ss = s + lane;
            bool hit = (ss < E) && (__ldg(labels + ss) == cI);
            unsigned m = __ballot_sync(0xffffffffu, hit);
            while (m) {
                int j = __ffs(m) - 1;
                m &= m - 1;
                const ulonglong2* h =
                    reinterpret_cast<const ulonglong2*>(hidden + (size_t)(s + j) * DIM);
                ulonglong2 a = __ldg(h + lane);
                ulonglong2 b = __ldg(h + lane + 32);
                ulonglong2 c = __ldg(h + lane + 64);
                ulonglong2 d = __ldg(h + lane + 96);
                ADD2(F[0], F[0], a.x); ADD2(F[1], F[1], a.y);
                ADD2(F[2], F[2], b.x); ADD2(F[3], F[3], b.y);
                ADD2(F[4], F[4], c.x); ADD2(F[5], F[5], c.y);
                ADD2(F[6], F[6], d.x); ADD2(F[7], F[7], d.y);
            }
        }

        // projection: 4 groups of 4 filters; fold + write per group
#pragma unroll
        for (int g = 0; g < 4; g++) {
            float sc[4];
#pragma unroll
            for (int jj = 0; jj < 4; jj++) {
                const int f = 4 * g + jj;
                u64 acc = 0ull;
                {
                    ulonglong2 wa = W2[f * 128 + lane];
                    ulonglong2 wb = W2[f * 128 + lane + 32];
                    FMA2(acc, F[0], wa.x, acc);
                    FMA2(acc, F[1], wa.y, acc);
                    FMA2(acc, F[2], wb.x, acc);
                    FMA2(acc, F[3], wb.y, acc);
                }
                {
                    ulonglong2 wc = W2[f * 128 + lane + 64];
                    ulonglong2 wd = W2[f * 128 + lane + 96];
                    FMA2(acc, F[4], wc.x, acc);
                    FMA2(acc, F[5], wc.y, acc);
                    FMA2(acc, F[6], wd.x, acc);
                    FMA2(acc, F[7], wd.y, acc);
                }
                float2 p = *reinterpret_cast<float2*>(&acc);
                sc[jj] = p.x + p.y;
            }
            fold_write(sc, out + (size_t)O * NFINE + 4 * g, lane);
        }
    }
}

extern "C" void kernel_launch(void* const* d_in, const int* in_sizes, int n_in,
                              void* d_out, int out_size)
{
    const float* hidden = (const float*)d_in[0];
    const float* slot   = (const float*)d_in[1];
    const int*   labels = (const int*)d_in[2];
    const int*   pB     = (const int*)d_in[3];
    const int*   pI     = (const int*)d_in[4];
    float* out = (float*)d_out;

    void* ctr_ptr = nullptr;
    cudaGetSymbolAddress(&ctr_ptr, g_ctr);
    cudaMemsetAsync(ctr_ptr, 0, 2 * sizeof(int), 0);
    cudaMemsetAsync(out, 0, (size_t)out_size * sizeof(float), 0);

    span_index_kernel<<<BATCH, 256>>>(labels, pB);
    span_project_kernel<<<148 * 4, 256>>>(hidden, slot, labels, pI, out);
}